// round 3
// baseline (speedup 1.0000x reference)
#include <cuda_runtime.h>

// Problem constants (fixed by the reference)
#define TT     2048
#define CELLS  2048           // B*H
#define NPAIR  (CELLS / 2)    // 1024 threads, 2 adjacent cells each
#define CHUNK  16
#define NCHUNK (TT / CHUNK)   // 128 (even)

// ---------------------------------------------------------------------------
// Kernel A: serial state scan, 2 adjacent cells per thread.
// forcings viewed as [T, NPAIR] float4 (P0,PET0,P1,PET1)
// states_out viewed as [T, NPAIR] float4 (S1_0,S2_0,S1_1,S2_1)
// Double-buffered register prefetch, statically named buffers (no dynamic idx).
// ---------------------------------------------------------------------------
__global__ __launch_bounds__(32, 1)
void scan_kernel(const float4* __restrict__ F4,    // forcings
                 const float4* __restrict__ S04,   // initial states [NPAIR]
                 const float4* __restrict__ P4,    // params [CELLS] float4
                 float4* __restrict__ ST4)         // states_out
{
    const int pair = blockIdx.x * 32 + threadIdx.x;

    // ---- parameter transform (once, both cells) ----
    const float4 ua = P4[2 * pair + 0];
    const float4 ub = P4[2 * pair + 1];

    const float smaxa = 10.0f  + 490.0f  * ua.x;
    const float k1a   = 0.01f  + 0.89f   * ua.y;
    const float k2a   = 0.001f + 0.199f  * ua.z;
    const float kba   = 0.001f + 0.099f  * ua.w;
    const float smaxb = 10.0f  + 490.0f  * ub.x;
    const float k1b   = 0.01f  + 0.89f   * ub.y;
    const float k2b   = 0.001f + 0.199f  * ub.z;
    const float kbb   = 0.001f + 0.099f  * ub.w;

    const float inva = 1.0f / smaxa,      invb = 1.0f / smaxb;
    const float c1a  = 1.0f - k1a - k2a,  c1b  = 1.0f - k1b - k2b;
    const float c2a  = 1.0f - kba,        c2b  = 1.0f - kbb;

    const float4 s0 = S04[pair];
    float S1a = s0.x, S2a = s0.y, S1b = s0.z, S2b = s0.w;

    const float4* __restrict__ F  = F4  + pair;
    float4*       __restrict__ ST = ST4 + pair;

#define STEP_BODY(fv, stptr)                                     \
    do {                                                         \
        const float Pa = (fv).x, Ea = (fv).y;                    \
        const float Pb = (fv).z, Eb = (fv).w;                    \
        const float aa = Ea * inva;                              \
        const float ab = Eb * invb;                              \
        const float eta = fminf(S1a * aa, Ea);                   \
        const float etb = fminf(S1b * ab, Eb);                   \
        const float pca = k2a * S1a;                             \
        const float pcb = k2b * S1b;                             \
        S1a = fmaxf(fmaf(S1a, c1a, Pa) - eta, 0.0f);             \
        S1b = fmaxf(fmaf(S1b, c1b, Pb) - etb, 0.0f);             \
        S2a = fmaxf(fmaf(S2a, c2a, pca), 0.0f);                  \
        S2b = fmaxf(fmaf(S2b, c2b, pcb), 0.0f);                  \
        *(stptr) = make_float4(S1a, S2a, S1b, S2b);              \
    } while (0)

    float4 bufA[CHUNK], bufB[CHUNK];

    // preload chunk 0 into bufA
#pragma unroll
    for (int i = 0; i < CHUNK; i++)
        bufA[i] = F[i * NPAIR];

#pragma unroll 1
    for (int cp = 0; cp < NCHUNK / 2; cp++) {
        const int c0 = 2 * cp;

        // prefetch chunk c0+1 into bufB (always valid)
        {
            const float4* Fn = F + (c0 + 1) * CHUNK * NPAIR;
#pragma unroll
            for (int i = 0; i < CHUNK; i++)
                bufB[i] = Fn[i * NPAIR];
        }

        // process chunk c0 from bufA
        {
            float4* STc = ST + c0 * CHUNK * NPAIR;
#pragma unroll
            for (int i = 0; i < CHUNK; i++)
                STEP_BODY(bufA[i], STc + i * NPAIR);
        }

        // prefetch chunk c0+2 into bufA (skip on last pair)
        if (cp + 1 < NCHUNK / 2) {
            const float4* Fn = F + (c0 + 2) * CHUNK * NPAIR;
#pragma unroll
            for (int i = 0; i < CHUNK; i++)
                bufA[i] = Fn[i * NPAIR];
        }

        // process chunk c0+1 from bufB
        {
            float4* STc = ST + (c0 + 1) * CHUNK * NPAIR;
#pragma unroll
            for (int i = 0; i < CHUNK; i++)
                STEP_BODY(bufB[i], STc + i * NPAIR);
        }
    }
#undef STEP_BODY
}

// ---------------------------------------------------------------------------
// Kernel B: fluxes from (shifted) states. Fully parallel, memory-bound.
//   flux_t = f(states_{t-1}, forcings_t, params), states_{-1} = states0
// ---------------------------------------------------------------------------
__global__ __launch_bounds__(256)
void flux_kernel(const float* __restrict__ forcings,   // [T, CELLS, 2]
                 const float* __restrict__ states0,    // [CELLS, 2]
                 const float* __restrict__ params,     // [CELLS, 4]
                 const float* __restrict__ states_seq, // [T, CELLS, 2]
                 float* __restrict__ fluxes)           // [T, CELLS, 4]
{
    const int idx  = blockIdx.x * blockDim.x + threadIdx.x; // t*CELLS + cell
    const int cell = idx & (CELLS - 1);
    const int t    = idx >> 11;    // CELLS = 2048 = 2^11

    const float2 f = reinterpret_cast<const float2*>(forcings)[idx];
    const float2 s = (t == 0)
        ? reinterpret_cast<const float2*>(states0)[cell]
        : reinterpret_cast<const float2*>(states_seq)[idx - CELLS];

    const float4 u = reinterpret_cast<const float4*>(params)[cell];
    const float smax = 10.0f  + 490.0f  * u.x;
    const float k1   = 0.01f  + 0.89f   * u.y;
    const float k2   = 0.001f + 0.199f  * u.z;
    const float kb   = 0.001f + 0.099f  * u.w;

    const float frac = fminf(fmaxf(s.x * (1.0f / smax), 0.0f), 1.0f);
    const float et   = f.y * frac;
    const float q1   = k1 * s.x;
    const float perc = k2 * s.x;
    const float qb   = kb * s.y;

    reinterpret_cast<float4*>(fluxes)[idx] = make_float4(et, q1, perc, qb);
}

extern "C" void kernel_launch(void* const* d_in, const int* in_sizes, int n_in,
                              void* d_out, int out_size)
{
    const float* forcings = (const float*)d_in[0];   // [T,B,H,2]
    const float* states0  = (const float*)d_in[1];   // [B,H,2]
    const float* params   = (const float*)d_in[2];   // [B,H,4]

    float* out = (float*)d_out;
    float* fluxes_out = out;                                   // [T,B,H,4]
    float* states_out = out + (size_t)TT * CELLS * 4;          // [T,B,H,2]

    scan_kernel<<<NPAIR / 32, 32>>>(
        reinterpret_cast<const float4*>(forcings),
        reinterpret_cast<const float4*>(states0),
        reinterpret_cast<const float4*>(params),
        reinterpret_cast<float4*>(states_out));

    flux_kernel<<<(TT * CELLS) / 256, 256>>>(forcings, states0, params,
                                             states_out, fluxes_out);
}

// round 4
// speedup vs baseline: 1.9752x; 1.9752x over previous
#include <cuda_runtime.h>

// Problem constants (fixed by the reference)
#define TT     2048
#define CELLS  2048           // B*H
#define NSEG   32             // time segments
#define SEGLEN (TT / NSEG)    // 64 steps per segment
#define CHUNK  16             // pass-1 forcing prefetch chunk
#define NPAIRC (TT / (2 * CHUNK))  // 64 chunk-pairs in pass 1

// Scratch: boundary states at t = 64, 128, ..., 1984 (seg index 1..31).
__device__ float2 g_bound[NSEG * CELLS];

// ---------------------------------------------------------------------------
// Pass 1: serial boundary scan. 1 thread per cell, 64 warps, no bulk stores.
// Shortened S1 chain:
//   S1' = max( fma(S1, c1 - E/smax, P), max(fma(S1, c1, P - E), 0) )
// which equals max(S1 + P - et - q1 - perc, 0) with et = min(S1*E/smax, E).
// ---------------------------------------------------------------------------
__global__ __launch_bounds__(32, 1)
void pass1_kernel(const float2* __restrict__ F2,   // forcings [T, CELLS]
                  const float2* __restrict__ S02,  // initial states [CELLS]
                  const float4* __restrict__ P4)   // params [CELLS]
{
    const int cell = blockIdx.x * 32 + threadIdx.x;

    const float4 u = P4[cell];
    const float smax = 10.0f  + 490.0f  * u.x;
    const float k1   = 0.01f  + 0.89f   * u.y;
    const float k2   = 0.001f + 0.199f  * u.z;
    const float kb   = 0.001f + 0.099f  * u.w;

    const float inv  = 1.0f / smax;
    const float c1   = 1.0f - k1 - k2;
    const float c2   = 1.0f - kb;

    float2 s = S02[cell];
    float S1 = s.x, S2 = s.y;

    const float2* __restrict__ F = F2 + cell;

#define P1_STEP(fv)                                              \
    do {                                                         \
        const float Pf  = (fv).x;                                \
        const float Ef  = (fv).y;                                \
        const float aa  = Ef * inv;          /* off-chain */     \
        const float caa = c1 - aa;           /* off-chain */     \
        const float pme = Pf - Ef;           /* off-chain */     \
        const float prc = k2 * S1;           /* old S1    */     \
        const float t1  = fmaf(S1, caa, Pf);                     \
        const float t2  = fmaf(S1, c1, pme);                     \
        const float m   = fmaxf(t2, 0.0f);                       \
        S1 = fmaxf(t1, m);                                       \
        S2 = fmaxf(fmaf(S2, c2, prc), 0.0f);                     \
    } while (0)

    float2 bufA[CHUNK], bufB[CHUNK];

    // preload chunk 0
#pragma unroll
    for (int i = 0; i < CHUNK; i++)
        bufA[i] = F[i * CELLS];

#pragma unroll 1
    for (int cp = 0; cp < NPAIRC; cp++) {
        // prefetch chunk 2cp+1 -> bufB
        {
            const float2* Fn = F + (2 * cp + 1) * CHUNK * CELLS;
#pragma unroll
            for (int i = 0; i < CHUNK; i++)
                bufB[i] = Fn[i * CELLS];
        }
        // process chunk 2cp from bufA
#pragma unroll
        for (int i = 0; i < CHUNK; i++)
            P1_STEP(bufA[i]);

        // prefetch chunk 2cp+2 -> bufA
        if (cp + 1 < NPAIRC) {
            const float2* Fn = F + (2 * cp + 2) * CHUNK * CELLS;
#pragma unroll
            for (int i = 0; i < CHUNK; i++)
                bufA[i] = Fn[i * CELLS];
        }
        // process chunk 2cp+1 from bufB
#pragma unroll
        for (int i = 0; i < CHUNK; i++)
            P1_STEP(bufB[i]);

        // after pair cp, 32*(cp+1) steps are done; boundary every 64 steps
        if ((cp & 1) && cp != NPAIRC - 1) {
            const int seg = (cp + 1) >> 1;     // 1..31
            g_bound[seg * CELLS + cell] = make_float2(S1, S2);
        }
    }
#undef P1_STEP
}

// ---------------------------------------------------------------------------
// Pass 2: parallel segment replay. One thread = (cell, segment).
// Replays SEGLEN steps from the boundary state, writing fluxes AND states
// with reference-faithful arithmetic. Memory-bound by design.
// ---------------------------------------------------------------------------
__global__ __launch_bounds__(256)
void pass2_kernel(const float2* __restrict__ F2,   // forcings [T, CELLS]
                  const float2* __restrict__ S02,  // initial states [CELLS]
                  const float4* __restrict__ P4,   // params [CELLS]
                  float4* __restrict__ FX4,        // fluxes [T, CELLS]
                  float2* __restrict__ ST2)        // states [T, CELLS]
{
    const int cell = blockIdx.x * 256 + threadIdx.x;
    const int seg  = blockIdx.y;
    const int t0   = seg * SEGLEN;

    const float4 u = P4[cell];
    const float smax = 10.0f  + 490.0f  * u.x;
    const float k1   = 0.01f  + 0.89f   * u.y;
    const float k2   = 0.001f + 0.199f  * u.z;
    const float kb   = 0.001f + 0.099f  * u.w;
    const float inv  = 1.0f / smax;

    float2 s = (seg == 0) ? S02[cell] : g_bound[seg * CELLS + cell];
    float S1 = s.x, S2 = s.y;

    const float2* __restrict__ F  = F2  + (size_t)t0 * CELLS + cell;
    float4*       __restrict__ FX = FX4 + (size_t)t0 * CELLS + cell;
    float2*       __restrict__ ST = ST2 + (size_t)t0 * CELLS + cell;

#pragma unroll 4
    for (int i = 0; i < SEGLEN; i++) {
        const float2 f = F[i * CELLS];
        const float P   = f.x;
        const float PET = f.y;

        const float frac = fminf(S1 * inv, 1.0f);   // S1 >= 0 always
        const float et   = PET * frac;
        const float q1   = k1 * S1;
        const float perc = k2 * S1;
        const float qb   = kb * S2;

        FX[i * CELLS] = make_float4(et, q1, perc, qb);

        S1 = fmaxf(S1 + P - et - q1 - perc, 0.0f);
        S2 = fmaxf(S2 + perc - qb, 0.0f);

        ST[i * CELLS] = make_float2(S1, S2);
    }
}

extern "C" void kernel_launch(void* const* d_in, const int* in_sizes, int n_in,
                              void* d_out, int out_size)
{
    const float* forcings = (const float*)d_in[0];   // [T,B,H,2]
    const float* states0  = (const float*)d_in[1];   // [B,H,2]
    const float* params   = (const float*)d_in[2];   // [B,H,4]

    float* out = (float*)d_out;
    float* fluxes_out = out;                                   // [T,B,H,4]
    float* states_out = out + (size_t)TT * CELLS * 4;          // [T,B,H,2]

    pass1_kernel<<<CELLS / 32, 32>>>(
        reinterpret_cast<const float2*>(forcings),
        reinterpret_cast<const float2*>(states0),
        reinterpret_cast<const float4*>(params));

    pass2_kernel<<<dim3(CELLS / 256, NSEG), 256>>>(
        reinterpret_cast<const float2*>(forcings),
        reinterpret_cast<const float2*>(states0),
        reinterpret_cast<const float4*>(params),
        reinterpret_cast<float4*>(fluxes_out),
        reinterpret_cast<float2*>(states_out));
}